// round 2
// baseline (speedup 1.0000x reference)
#include <cuda_runtime.h>
#include <cstdint>

// ---------------------------------------------------------------------------
// OnlyLinear chain: y = W8(...(W0 x + b0)...) + b8  with NO activations.
// Fold the whole chain into a single affine map  y = W_eff x + b_eff,
// W_eff = W8*...*W0 [10,784], then run one HBM-bound GEMV-like pass.
// ---------------------------------------------------------------------------

#define K_IN   784
#define N_OUT  10

// Scratch (device globals: no allocations allowed in kernel_launch)
__device__ float g_A[10 * 69];      // folded W8..W1  [10, 69]
__device__ float g_beff[N_OUT];     // folded bias
__device__ float g_Weff[N_OUT * K_IN];  // final [10, 784]

// ---------------------------------------------------------------------------
// Kernel 1: fold W8..W1 and the full bias chain. Single block.
//   A <- W8;  beff <- b8
//   for j = 7..1:  beff += A @ b_j ;  A <- A @ W_j
//   beff += A @ b0   (W0 handled by kernel 2)
// Shapes: W_j is [n_out_j, n_in_j] row-major.
// ---------------------------------------------------------------------------
__device__ __forceinline__ void fold_step(
    float* A, float* T, float* beff,
    const float* W, const float* b,
    int n /* current inner dim = rows of W */, int m /* new inner dim = cols of W */,
    int t, int nthreads)
{
    // bias: beff[r] += sum_k A[r*n+k] * b[k]   (reads old A, no race)
    if (t < N_OUT) {
        float s = 0.f;
        for (int k = 0; k < n; ++k) s += A[t * n + k] * b[k];
        beff[t] += s;
    }
    // T[r,c] = sum_k A[r,k] * W[k,c]
    for (int idx = t; idx < N_OUT * m; idx += nthreads) {
        int r = idx / m, c = idx % m;
        float s = 0.f;
        for (int k = 0; k < n; ++k) s += A[r * n + k] * W[k * m + c];
        T[idx] = s;
    }
    __syncthreads();
    for (int idx = t; idx < N_OUT * m; idx += nthreads) A[idx] = T[idx];
    __syncthreads();
}

__global__ void fold_small(
    const float* W1, const float* b1, const float* W2, const float* b2,
    const float* W3, const float* b3, const float* W4, const float* b4,
    const float* W5, const float* b5, const float* W6, const float* b6,
    const float* W7, const float* b7, const float* W8, const float* b8,
    const float* b0)
{
    __shared__ float A[10 * 69];
    __shared__ float T[10 * 69];
    __shared__ float beff[N_OUT];

    const int t = threadIdx.x;
    const int nt = blockDim.x;

    if (t < 100) A[t] = W8[t];
    if (t < N_OUT) beff[t] = b8[t];
    __syncthreads();

    // layers 7..3: [10,10]
    fold_step(A, T, beff, W7, b7, 10, 10, t, nt);
    fold_step(A, T, beff, W6, b6, 10, 10, t, nt);
    fold_step(A, T, beff, W5, b5, 10, 10, t, nt);
    fold_step(A, T, beff, W4, b4, 10, 10, t, nt);
    fold_step(A, T, beff, W3, b3, 10, 10, t, nt);
    // layer 2: W2 [10,31] -> A [10,31]
    fold_step(A, T, beff, W2, b2, 10, 31, t, nt);
    // layer 1: W1 [31,69] -> A [10,69]
    fold_step(A, T, beff, W1, b1, 31, 69, t, nt);

    // bias contribution of layer 0: beff += A @ b0
    if (t < N_OUT) {
        float s = 0.f;
        for (int k = 0; k < 69; ++k) s += A[t * 69 + k] * b0[k];
        g_beff[t] = beff[t] + s;
    }
    // publish A
    for (int idx = t; idx < 10 * 69; idx += nt) g_A[idx] = A[idx];
}

// ---------------------------------------------------------------------------
// Kernel 2: W_eff[10,784] = A[10,69] @ W0[69,784]
// ---------------------------------------------------------------------------
__global__ void fold_W0(const float* __restrict__ W0)
{
    int idx = blockIdx.x * blockDim.x + threadIdx.x;
    if (idx >= N_OUT * K_IN) return;
    int r = idx / K_IN, c = idx % K_IN;
    float s = 0.f;
#pragma unroll 1
    for (int k = 0; k < 69; ++k) s += g_A[r * 69 + k] * W0[k * K_IN + c];
    g_Weff[idx] = s;
}

// ---------------------------------------------------------------------------
// Kernel 3: the HBM-bound pass.  One row per thread.
// W_eff staged in shared (uniform-address broadcast loads), accumulation in
// packed f32x2 (FFMA2) to keep the FMA pipe well under the memory roof.
// ---------------------------------------------------------------------------
__device__ __forceinline__ void ffma2(unsigned long long& acc,
                                      unsigned long long a,
                                      unsigned long long b)
{
    asm("fma.rn.f32x2 %0, %1, %2, %0;" : "+l"(acc) : "l"(a), "l"(b));
}

__device__ __forceinline__ unsigned long long pack2(float lo, float hi)
{
    unsigned long long r;
    asm("mov.b64 %0, {%1, %2};" : "=l"(r) : "f"(lo), "f"(hi));
    return r;
}

__global__ __launch_bounds__(256) void gemv_folded(
    const float* __restrict__ x, float* __restrict__ y, int B)
{
    __shared__ float sW[N_OUT * K_IN];   // 31360 B
    __shared__ float sb[N_OUT];

    for (int i = threadIdx.x; i < N_OUT * K_IN; i += 256) sW[i] = g_Weff[i];
    if (threadIdx.x < N_OUT) sb[threadIdx.x] = g_beff[threadIdx.x];
    __syncthreads();

    const int row = blockIdx.x * 256 + threadIdx.x;
    if (row >= B) return;

    const float4* __restrict__ xr =
        reinterpret_cast<const float4*>(x) + (size_t)row * (K_IN / 4);

    unsigned long long acc[N_OUT];
#pragma unroll
    for (int j = 0; j < N_OUT; ++j) acc[j] = 0ull;  // (0.0f, 0.0f)

#pragma unroll 4
    for (int i = 0; i < K_IN / 4; ++i) {
        float4 xv = xr[i];
        unsigned long long xlo = pack2(xv.x, xv.y);
        unsigned long long xhi = pack2(xv.z, xv.w);
        const int base = 4 * i;
#pragma unroll
        for (int j = 0; j < N_OUT; ++j) {
            // sW row offset j*784 is 8B-aligned (784*4 % 8 == 0); base*4 % 8 == 0
            unsigned long long wlo =
                *reinterpret_cast<const unsigned long long*>(&sW[j * K_IN + base]);
            unsigned long long whi =
                *reinterpret_cast<const unsigned long long*>(&sW[j * K_IN + base + 2]);
            ffma2(acc[j], xlo, wlo);
            ffma2(acc[j], xhi, whi);
        }
    }

    float r[N_OUT];
#pragma unroll
    for (int j = 0; j < N_OUT; ++j) {
        float lo, hi;
        asm("mov.b64 {%0, %1}, %2;" : "=f"(lo), "=f"(hi) : "l"(acc[j]));
        r[j] = lo + hi + sb[j];
    }

    // y row base = row*10 floats = 40*row bytes -> 8B aligned: 5x STG.64
    float2* out2 = reinterpret_cast<float2*>(y + (size_t)row * N_OUT);
#pragma unroll
    for (int j = 0; j < N_OUT / 2; ++j) {
        float2 v; v.x = r[2 * j]; v.y = r[2 * j + 1];
        out2[j] = v;
    }
}

// ---------------------------------------------------------------------------
// kernel_launch: inputs in metadata order: x, W0,b0, W1,b1, ..., W8,b8
// ---------------------------------------------------------------------------
extern "C" void kernel_launch(void* const* d_in, const int* in_sizes, int n_in,
                              void* d_out, int out_size)
{
    const float* x = (const float*)d_in[0];
    const float* W[9];
    const float* b[9];
    for (int i = 0; i < 9; ++i) {
        W[i] = (const float*)d_in[1 + 2 * i];
        b[i] = (const float*)d_in[2 + 2 * i];
    }
    const int B = in_sizes[0] / K_IN;

    fold_small<<<1, 768>>>(W[1], b[1], W[2], b[2], W[3], b[3], W[4], b[4],
                           W[5], b[5], W[6], b[6], W[7], b[7], W[8], b[8],
                           b[0]);
    fold_W0<<<(N_OUT * K_IN + 255) / 256, 256>>>(W[0]);

    float* y = (float*)d_out;
    gemv_folded<<<(B + 255) / 256, 256>>>(x, y, B);
}

// round 5
// speedup vs baseline: 1.0828x; 1.0828x over previous
#include <cuda_runtime.h>
#include <cstdint>

// ---------------------------------------------------------------------------
// OnlyLinear chain: y = W8(...(W0 x + b0)...) + b8, NO activations.
// Fold into y = W_eff x + b_eff (W_eff [10,784]), then one DRAM-bound pass.
// R2: (a) single fold kernel with smem-prefetched weights,
//     (b) gemv with coalesced smem-staged x tiles (kills nL=32 L1tex storm).
// ---------------------------------------------------------------------------

#define K_IN   784
#define N_OUT  10

__device__ float g_Weff[N_OUT * K_IN];
__device__ float g_beff[N_OUT];

// ---------------------------------------------------------------------------
// fold_all: one block.  1) prefetch W1..W8, b0..b8 into smem (parallel LDGs)
// 2) fold A = W8..W1 and full bias chain in smem  3) W_eff = A @ W0 with
// coalesced W0 loads (thread = output column).
// ---------------------------------------------------------------------------
__device__ __forceinline__ void fold_step_sm(
    float* A, float* T, float* beff,
    const float* W, const float* b, int n, int m, int t)
{
    if (t < N_OUT) {                       // beff += A @ b (reads old A)
        float s = 0.f;
        for (int k = 0; k < n; ++k) s += A[t * n + k] * b[k];
        beff[t] += s;
    }
    if (t < N_OUT * m) {                   // T = A @ W
        int r = t / m, c = t % m;
        float s = 0.f;
        for (int k = 0; k < n; ++k) s += A[r * n + k] * W[k * m + c];
        T[t] = s;
    }
    __syncthreads();
    if (t < N_OUT * m) A[t] = T[t];
    __syncthreads();
}

__global__ void fold_all(
    const float* __restrict__ W0, const float* __restrict__ b0,
    const float* __restrict__ W1, const float* __restrict__ b1,
    const float* __restrict__ W2, const float* __restrict__ b2,
    const float* __restrict__ W3, const float* __restrict__ b3,
    const float* __restrict__ W4, const float* __restrict__ b4,
    const float* __restrict__ W5, const float* __restrict__ b5,
    const float* __restrict__ W6, const float* __restrict__ b6,
    const float* __restrict__ W7, const float* __restrict__ b7,
    const float* __restrict__ W8, const float* __restrict__ b8)
{
    __shared__ float A[10 * 69], T[10 * 69], beff[N_OUT];
    __shared__ float sw[3049];   // W1(2139) W2(310) W3..W8(6*100)
    __shared__ float sbv[170];   // b0(69) b1(31) b2..b8(7*10)

    const int t = threadIdx.x;
    const int nt = blockDim.x;

    // --- prefetch everything small (independent loads, latency paid once) ---
    float* sW1 = sw;          float* sW2 = sw + 2139;
    float* sW3 = sw + 2449;   float* sW4 = sw + 2549;
    float* sW5 = sw + 2649;   float* sW6 = sw + 2749;
    float* sW7 = sw + 2849;   float* sW8 = sw + 2949;
    float* sb0 = sbv;         float* sb1 = sbv + 69;
    float* sb2 = sbv + 100;   float* sb3 = sbv + 110;
    float* sb4 = sbv + 120;   float* sb5 = sbv + 130;
    float* sb6 = sbv + 140;   float* sb7 = sbv + 150;
    float* sb8 = sbv + 160;

    for (int i = t; i < 2139; i += nt) sW1[i] = W1[i];
    for (int i = t; i < 310;  i += nt) sW2[i] = W2[i];
    if (t < 100) { sW3[t] = W3[t]; sW4[t] = W4[t]; sW5[t] = W5[t];
                   sW6[t] = W6[t]; sW7[t] = W7[t]; sW8[t] = W8[t]; }
    if (t < 69) sb0[t] = b0[t];
    if (t < 31) sb1[t] = b1[t];
    if (t < 10) { sb2[t] = b2[t]; sb3[t] = b3[t]; sb4[t] = b4[t];
                  sb5[t] = b5[t]; sb6[t] = b6[t]; sb7[t] = b7[t];
                  sb8[t] = b8[t]; }
    if (t < 100) A[t] = sW8[t] * 0.f;   // placeholder, set after sync
    __syncthreads();

    if (t < 100) A[t] = sW8[t];
    if (t < N_OUT) beff[t] = sb8[t];
    __syncthreads();

    fold_step_sm(A, T, beff, sW7, sb7, 10, 10, t);
    fold_step_sm(A, T, beff, sW6, sb6, 10, 10, t);
    fold_step_sm(A, T, beff, sW5, sb5, 10, 10, t);
    fold_step_sm(A, T, beff, sW4, sb4, 10, 10, t);
    fold_step_sm(A, T, beff, sW3, sb3, 10, 10, t);
    fold_step_sm(A, T, beff, sW2, sb2, 10, 31, t);   // -> A [10,31]
    fold_step_sm(A, T, beff, sW1, sb1, 31, 69, t);   // -> A [10,69]

    // beff += A @ b0 ; publish bias
    if (t < N_OUT) {
        float s = 0.f;
        for (int k = 0; k < 69; ++k) s += A[t * 69 + k] * sb0[k];
        g_beff[t] = beff[t] + s;
    }
    __syncthreads();   // A final for everyone

    // --- W_eff = A @ W0 : thread t owns output column t (coalesced W0) ---
    if (t < K_IN) {
        float acc[N_OUT];
#pragma unroll
        for (int r = 0; r < N_OUT; ++r) acc[r] = 0.f;
#pragma unroll 4
        for (int k = 0; k < 69; ++k) {
            float w0 = W0[k * K_IN + t];
#pragma unroll
            for (int r = 0; r < N_OUT; ++r) acc[r] += A[r * 69 + k] * w0;
        }
#pragma unroll
        for (int r = 0; r < N_OUT; ++r) g_Weff[r * K_IN + t] = acc[r];
    }
}

// ---------------------------------------------------------------------------
// gemv: block = 256 threads = 256 rows.  Loop over 14 chunks of 56 columns:
// stage x-tile into smem COALESCED, then thread-per-row computes from smem
// (x: padded stride-60 LDS.128 conflict-free; W: warp-uniform broadcast).
// Accumulate in packed f32x2 (FFMA2).
// ---------------------------------------------------------------------------
#define RPB     256          // rows per block
#define CHUNK   56           // columns per chunk  (14 * 56 = 784)
#define NCHUNK  14
#define XSTRIDE 60           // padded floats per row in smem (bank-safe, 16B)

// dynamic smem layout: sW [0,7840) floats, xs [7840, 7840+RPB*XSTRIDE)
#define SMEM_FLOATS (7840 + RPB * XSTRIDE)

__device__ __forceinline__ void ffma2(unsigned long long& acc,
                                      unsigned long long a,
                                      unsigned long long b)
{
    asm("fma.rn.f32x2 %0, %1, %2, %0;" : "+l"(acc) : "l"(a), "l"(b));
}

__global__ __launch_bounds__(256) void gemv_folded(
    const float* __restrict__ x, float* __restrict__ y, int B)
{
    extern __shared__ float smem[];
    float* sW = smem;
    float* xs = smem + 7840;

    const int tid = threadIdx.x;
    const int row0 = blockIdx.x * RPB;

    for (int i = tid; i < N_OUT * K_IN; i += 256) sW[i] = g_Weff[i];
    // (fenced by the first __syncthreads inside the chunk loop)

    unsigned long long acc[N_OUT];
#pragma unroll
    for (int j = 0; j < N_OUT; ++j) acc[j] = 0ull;

#pragma unroll 1
    for (int chunk = 0; chunk < NCHUNK; ++chunk) {
        const int c0 = chunk * CHUNK;

        // ---- stage x[row0:row0+256, c0:c0+56] coalesced ----
#pragma unroll
        for (int i = 0; i < NCHUNK; ++i) {           // 14 float4 per thread
            int idx = i * 256 + tid;                 // 0..3583
            int r   = idx / 14;
            int c4  = idx - r * 14;
            if (row0 + r < B) {
                float4 v = *reinterpret_cast<const float4*>(
                    x + (size_t)(row0 + r) * K_IN + c0 + 4 * c4);
                *reinterpret_cast<float4*>(xs + r * XSTRIDE + 4 * c4) = v;
            }
        }
        __syncthreads();

        // ---- compute: thread = row, all 10 outputs ----
        const float* xrow = xs + tid * XSTRIDE;
#pragma unroll
        for (int c4 = 0; c4 < NCHUNK; ++c4) {
            ulonglong2 xv = *reinterpret_cast<const ulonglong2*>(xrow + 4 * c4);
#pragma unroll
            for (int j = 0; j < N_OUT; ++j) {
                ulonglong2 wv = *reinterpret_cast<const ulonglong2*>(
                    sW + j * K_IN + c0 + 4 * c4);       // warp-uniform -> broadcast
                ffma2(acc[j], xv.x, wv.x);
                ffma2(acc[j], xv.y, wv.y);
            }
        }
        __syncthreads();
    }

    // ---- epilogue ----
    const int row = row0 + tid;
    if (row < B) {
        float2* out2 = reinterpret_cast<float2*>(y + (size_t)row * N_OUT);
#pragma unroll
        for (int p = 0; p < N_OUT / 2; ++p) {
            float lo0, hi0, lo1, hi1;
            asm("mov.b64 {%0, %1}, %2;" : "=f"(lo0), "=f"(hi0) : "l"(acc[2*p]));
            asm("mov.b64 {%0, %1}, %2;" : "=f"(lo1), "=f"(hi1) : "l"(acc[2*p+1]));
            float2 v;
            v.x = lo0 + hi0 + g_beff[2 * p];
            v.y = lo1 + hi1 + g_beff[2 * p + 1];
            out2[p] = v;
        }
    }
}

// ---------------------------------------------------------------------------
extern "C" void kernel_launch(void* const* d_in, const int* in_sizes, int n_in,
                              void* d_out, int out_size)
{
    const float* x = (const float*)d_in[0];
    const float* W[9];
    const float* b[9];
    for (int i = 0; i < 9; ++i) {
        W[i] = (const float*)d_in[1 + 2 * i];
        b[i] = (const float*)d_in[2 + 2 * i];
    }
    const int B = in_sizes[0] / K_IN;

    fold_all<<<1, 784>>>(W[0], b[0], W[1], b[1], W[2], b[2], W[3], b[3],
                         W[4], b[4], W[5], b[5], W[6], b[6], W[7], b[7],
                         W[8], b[8]);

    static int smem_bytes = SMEM_FLOATS * sizeof(float);
    cudaFuncSetAttribute(gemv_folded,
                         cudaFuncAttributeMaxDynamicSharedMemorySize,
                         smem_bytes);

    float* y = (float*)d_out;
    gemv_folded<<<(B + RPB - 1) / RPB, 256, smem_bytes>>>(x, y, B);
}

// round 7
// speedup vs baseline: 1.4235x; 1.3147x over previous
#include <cuda_runtime.h>
#include <cstdint>

// ---------------------------------------------------------------------------
// y = W8(...(W0 x + b0)...) + b8  ->  y = W_eff x + b_eff,  W_eff [10,784].
// R6: gemv with 4 rows/lane, 8 column-lanes/warp: W smem loads amortized over
// 16 rows; x read DIRECTLY from DRAM (coalesced, single-touch lines).
// ---------------------------------------------------------------------------

#define K_IN   784
#define N_OUT  10
#define SW_STRIDE 800   // padded W row stride in smem (cols 784..799 zeroed)

__device__ float g_A[10 * 69];
__device__ float g_beff[N_OUT];
__device__ float g_Weff[N_OUT * K_IN];

// ---------------------------------------------------------------------------
// fold_small: one block; fold W8..W1 + full bias chain (tiny FLOPs).
// ---------------------------------------------------------------------------
__device__ __forceinline__ void fold_step_sm(
    float* A, float* T, float* beff,
    const float* W, const float* b, int n, int m, int t)
{
    if (t < N_OUT) {
        float s = 0.f;
        for (int k = 0; k < n; ++k) s += A[t * n + k] * b[k];
        beff[t] += s;
    }
    if (t < N_OUT * m) {
        int r = t / m, c = t % m;
        float s = 0.f;
        for (int k = 0; k < n; ++k) s += A[r * n + k] * W[k * m + c];
        T[t] = s;
    }
    __syncthreads();
    if (t < N_OUT * m) A[t] = T[t];
    __syncthreads();
}

__global__ void fold_small(
    const float* __restrict__ b0,
    const float* __restrict__ W1, const float* __restrict__ b1,
    const float* __restrict__ W2, const float* __restrict__ b2,
    const float* __restrict__ W3, const float* __restrict__ b3,
    const float* __restrict__ W4, const float* __restrict__ b4,
    const float* __restrict__ W5, const float* __restrict__ b5,
    const float* __restrict__ W6, const float* __restrict__ b6,
    const float* __restrict__ W7, const float* __restrict__ b7,
    const float* __restrict__ W8, const float* __restrict__ b8)
{
    __shared__ float A[10 * 69], T[10 * 69], beff[N_OUT];
    __shared__ float sw[3049];
    __shared__ float sbv[170];

    const int t = threadIdx.x;
    const int nt = blockDim.x;

    float* sW1 = sw;          float* sW2 = sw + 2139;
    float* sW3 = sw + 2449;   float* sW4 = sw + 2549;
    float* sW5 = sw + 2649;   float* sW6 = sw + 2749;
    float* sW7 = sw + 2849;   float* sW8 = sw + 2949;
    float* sb0 = sbv;         float* sb1 = sbv + 69;
    float* sb2 = sbv + 100;   float* sb3 = sbv + 110;
    float* sb4 = sbv + 120;   float* sb5 = sbv + 130;
    float* sb6 = sbv + 140;   float* sb7 = sbv + 150;
    float* sb8 = sbv + 160;

    for (int i = t; i < 2139; i += nt) sW1[i] = W1[i];
    for (int i = t; i < 310;  i += nt) sW2[i] = W2[i];
    if (t < 100) { sW3[t] = W3[t]; sW4[t] = W4[t]; sW5[t] = W5[t];
                   sW6[t] = W6[t]; sW7[t] = W7[t]; sW8[t] = W8[t]; }
    if (t < 69) sb0[t] = b0[t];
    if (t < 31) sb1[t] = b1[t];
    if (t < 10) { sb2[t] = b2[t]; sb3[t] = b3[t]; sb4[t] = b4[t];
                  sb5[t] = b5[t]; sb6[t] = b6[t]; sb7[t] = b7[t];
                  sb8[t] = b8[t]; }
    __syncthreads();

    if (t < 100) A[t] = sW8[t];
    if (t < N_OUT) beff[t] = sb8[t];
    __syncthreads();

    fold_step_sm(A, T, beff, sW7, sb7, 10, 10, t);
    fold_step_sm(A, T, beff, sW6, sb6, 10, 10, t);
    fold_step_sm(A, T, beff, sW5, sb5, 10, 10, t);
    fold_step_sm(A, T, beff, sW4, sb4, 10, 10, t);
    fold_step_sm(A, T, beff, sW3, sb3, 10, 10, t);
    fold_step_sm(A, T, beff, sW2, sb2, 10, 31, t);
    fold_step_sm(A, T, beff, sW1, sb1, 31, 69, t);

    if (t < N_OUT) {
        float s = 0.f;
        for (int k = 0; k < 69; ++k) s += A[t * 69 + k] * sb0[k];
        g_beff[t] = beff[t] + s;
    }
    for (int i = t; i < 10 * 69; i += nt) g_A[i] = A[i];
}

// ---------------------------------------------------------------------------
// fold_W0: W_eff = A @ W0, parallel over 7 CTAs (DRAM pull of W0 spread out).
// thread t owns global output column; W0 loads coalesced.
// ---------------------------------------------------------------------------
__global__ void fold_W0(const float* __restrict__ W0)
{
    __shared__ float sA[10 * 69];
    const int tid = threadIdx.x;
    for (int i = tid; i < 690; i += 112) sA[i] = g_A[i];
    __syncthreads();

    const int c = blockIdx.x * 112 + tid;   // 7 * 112 = 784
    float acc[N_OUT];
#pragma unroll
    for (int r = 0; r < N_OUT; ++r) acc[r] = 0.f;
#pragma unroll 4
    for (int k = 0; k < 69; ++k) {
        float w0 = W0[k * K_IN + c];
#pragma unroll
        for (int r = 0; r < N_OUT; ++r) acc[r] += sA[r * 69 + k] * w0;
    }
#pragma unroll
    for (int r = 0; r < N_OUT; ++r) g_Weff[r * K_IN + c] = acc[r];
}

// ---------------------------------------------------------------------------
// gemv_direct: grid = B/128 CTAs x 256 threads.
// warp = 8 kg-lanes (columns) x 4 rg-groups; each lane owns 4 rows.
// Per warp-iter: 16 rows x 32 cols; x via 4 direct LDG.128; W via 10 LDS.128
// (conflict-free, 4-way broadcast). acc = f32x2 over column halves.
// ---------------------------------------------------------------------------
__device__ __forceinline__ void ffma2(unsigned long long& acc,
                                      unsigned long long a,
                                      unsigned long long b)
{
    asm("fma.rn.f32x2 %0, %1, %2, %0;" : "+l"(acc) : "l"(a), "l"(b));
}

__global__ __launch_bounds__(256, 2) void gemv_direct(
    const float* __restrict__ x, float* __restrict__ y, int B)
{
    __shared__ float sW[N_OUT * SW_STRIDE];   // 32000 B
    __shared__ float sb[N_OUT];

    const int tid = threadIdx.x;

    // stage W_eff (compact -> padded stride), zero the pad columns
    for (int i = tid; i < N_OUT * K_IN; i += 256) {
        int j = i / K_IN, c = i - j * K_IN;
        sW[j * SW_STRIDE + c] = g_Weff[i];
    }
    if (tid < N_OUT * (SW_STRIDE - K_IN)) {       // 160 pad elems
        int j = tid / (SW_STRIDE - K_IN);
        int c = K_IN + tid % (SW_STRIDE - K_IN);
        sW[j * SW_STRIDE + c] = 0.f;
    }
    if (tid < N_OUT) sb[tid] = g_beff[tid];
    __syncthreads();

    const int lane = tid & 31;
    const int warp = tid >> 5;
    const int kg = lane & 7;          // column lane 0..7
    const int rg = lane >> 3;         // row group 0..3
    const int row0 = blockIdx.x * 128 + warp * 16 + rg * 4;  // 4 rows

    const float* xbase = x + (size_t)row0 * K_IN;

    unsigned long long acc[N_OUT][4];
#pragma unroll
    for (int j = 0; j < N_OUT; ++j)
#pragma unroll
        for (int rr = 0; rr < 4; ++rr) acc[j][rr] = 0ull;

#pragma unroll 1
    for (int i = 0; i < 25; ++i) {
        const int c = 4 * kg + 32 * i;
        const bool cok = (c < K_IN);

        ulonglong2 xv[4];
#pragma unroll
        for (int rr = 0; rr < 4; ++rr) {
            if (cok && (row0 + rr < B)) {
                xv[rr] = *reinterpret_cast<const ulonglong2*>(
                    xbase + (size_t)rr * K_IN + c);
            } else {
                xv[rr].x = 0ull; xv[rr].y = 0ull;
            }
        }

#pragma unroll
        for (int j = 0; j < N_OUT; ++j) {
            // c < 800 always; pad cols are zero -> safe
            ulonglong2 w = *reinterpret_cast<const ulonglong2*>(
                &sW[j * SW_STRIDE + c]);
#pragma unroll
            for (int rr = 0; rr < 4; ++rr) {
                ffma2(acc[j][rr], xv[rr].x, w.x);
                ffma2(acc[j][rr], xv[rr].y, w.y);
            }
        }
    }

    // collapse f32x2 halves, then butterfly-reduce over the 8 kg lanes
    float s[N_OUT][4];
#pragma unroll
    for (int j = 0; j < N_OUT; ++j)
#pragma unroll
        for (int rr = 0; rr < 4; ++rr) {
            float lo, hi;
            asm("mov.b64 {%0, %1}, %2;" : "=f"(lo), "=f"(hi) : "l"(acc[j][rr]));
            s[j][rr] = lo + hi;
        }

#pragma unroll
    for (int m = 1; m <= 4; m <<= 1)
#pragma unroll
        for (int j = 0; j < N_OUT; ++j)
#pragma unroll
            for (int rr = 0; rr < 4; ++rr)
                s[j][rr] += __shfl_xor_sync(0xFFFFFFFFu, s[j][rr], m);

    // lanes kg = 0..4 write float2 (outputs 2*kg, 2*kg+1) for their 4 rows
    if (kg < 5) {
#pragma unroll
        for (int rr = 0; rr < 4; ++rr) {
            const int row = row0 + rr;
            if (row < B) {
                float2 v;
                v.x = s[2 * kg][rr]     + sb[2 * kg];
                v.y = s[2 * kg + 1][rr] + sb[2 * kg + 1];
                *reinterpret_cast<float2*>(y + (size_t)row * N_OUT + 2 * kg) = v;
            }
        }
    }
}

// ---------------------------------------------------------------------------
extern "C" void kernel_launch(void* const* d_in, const int* in_sizes, int n_in,
                              void* d_out, int out_size)
{
    const float* x = (const float*)d_in[0];
    const float* W[9];
    const float* b[9];
    for (int i = 0; i < 9; ++i) {
        W[i] = (const float*)d_in[1 + 2 * i];
        b[i] = (const float*)d_in[2 + 2 * i];
    }
    const int B = in_sizes[0] / K_IN;

    fold_small<<<1, 768>>>(b[0], W[1], b[1], W[2], b[2], W[3], b[3],
                           W[4], b[4], W[5], b[5], W[6], b[6],
                           W[7], b[7], W[8], b[8]);
    fold_W0<<<7, 112>>>(W[0]);

    float* y = (float*)d_out;
    gemv_direct<<<(B + 127) / 128, 256>>>(x, y, B);
}